// round 1
// baseline (speedup 1.0000x reference)
#include <cuda_runtime.h>
#include <math.h>

// Problem constants
#define B_   8
#define S_   1024
#define D_   1024
#define H_   8
#define HD_  128
#define PREFIX_LEN 77
#define MASKED_BIAS -10000.0f

// Scratch (no cudaMalloc allowed)
__device__ float g_qkv[B_ * S_ * 3 * D_];   // [B,S,3D]  96 MB
__device__ float g_attn[B_ * S_ * D_];      // [B,S,D]   32 MB

// ---------------------------------------------------------------------------
// SGEMM: C[M,N] = A[M,K] @ B[K,N] + bias[N]
// 128x128 tile, BK=8, 256 threads, 8x8 per thread. M,N,K divisible by tiles.
// ---------------------------------------------------------------------------
#define GBM 128
#define GBN 128
#define GBK 8

__global__ __launch_bounds__(256) void sgemm_bias(
    const float* __restrict__ A, const float* __restrict__ Bm,
    const float* __restrict__ bias, float* __restrict__ C,
    int M, int N, int K)
{
    __shared__ float As[GBK][GBM];
    __shared__ float Bs[GBK][GBN];

    const int t  = threadIdx.x;
    const int bm = blockIdx.y * GBM;
    const int bn = blockIdx.x * GBN;
    const int tx = t & 15;
    const int ty = t >> 4;

    const int arow = t >> 1;          // 0..127
    const int acol = (t & 1) * 4;     // 0 or 4
    const int brow = t >> 5;          // 0..7
    const int bcol = (t & 31) * 4;    // 0..124

    float acc[8][8];
    #pragma unroll
    for (int i = 0; i < 8; i++)
        #pragma unroll
        for (int j = 0; j < 8; j++) acc[i][j] = 0.0f;

    for (int k0 = 0; k0 < K; k0 += GBK) {
        float4 av = *(const float4*)&A[(long)(bm + arow) * K + k0 + acol];
        As[acol + 0][arow] = av.x;
        As[acol + 1][arow] = av.y;
        As[acol + 2][arow] = av.z;
        As[acol + 3][arow] = av.w;
        float4 bv = *(const float4*)&Bm[(long)(k0 + brow) * N + bn + bcol];
        *(float4*)&Bs[brow][bcol] = bv;
        __syncthreads();

        #pragma unroll
        for (int kk = 0; kk < GBK; kk++) {
            float a[8], b[8];
            *(float4*)&a[0] = *(const float4*)&As[kk][ty * 8];
            *(float4*)&a[4] = *(const float4*)&As[kk][ty * 8 + 4];
            *(float4*)&b[0] = *(const float4*)&Bs[kk][tx * 8];
            *(float4*)&b[4] = *(const float4*)&Bs[kk][tx * 8 + 4];
            #pragma unroll
            for (int i = 0; i < 8; i++)
                #pragma unroll
                for (int j = 0; j < 8; j++)
                    acc[i][j] = fmaf(a[i], b[j], acc[i][j]);
        }
        __syncthreads();
    }

    #pragma unroll
    for (int i = 0; i < 8; i++) {
        const int row = bm + ty * 8 + i;
        #pragma unroll
        for (int j = 0; j < 8; j += 4) {
            const int col = bn + tx * 8 + j;
            float4 o;
            o.x = acc[i][j + 0] + bias[col + 0];
            o.y = acc[i][j + 1] + bias[col + 1];
            o.z = acc[i][j + 2] + bias[col + 2];
            o.w = acc[i][j + 3] + bias[col + 3];
            *(float4*)&C[(long)row * N + col] = o;
        }
    }
}

// ---------------------------------------------------------------------------
// Fused flash attention (fp32). Grid: (S/64, B*H). 256 threads.
// 64 query rows per block, key tiles of 64, hd=128, online softmax.
// ---------------------------------------------------------------------------
#define ABM 64
#define ABN 64

// dyn smem: Qt[128][64] + KV(union Kt[128][64] / Vs[64][128]) + Ss[64][65] + stats
#define SS_LD 65
#define ATTN_SMEM_FLOATS (HD_*ABM + HD_*ABN + ABM*SS_LD + 3*ABM)
#define ATTN_SMEM_BYTES  (ATTN_SMEM_FLOATS * 4)

__global__ __launch_bounds__(256) void attn_kernel(
    const float* __restrict__ qkv,      // [B,S,3D]
    const float* __restrict__ amask,    // [B,1,1,S]
    float* __restrict__ aout)           // [B,S,D]
{
    extern __shared__ float sm[];
    float* Qt     = sm;                       // [128][64] Qt[d][m]
    float* KV     = Qt + HD_ * ABM;           // Kt[d][n] or Vs[n][d]
    float* Ss     = KV + HD_ * ABN;           // [64][65]
    float* rmax   = Ss + ABM * SS_LD;
    float* rsum   = rmax + ABM;
    float* rscale = rsum + ABM;

    const int t   = threadIdx.x;
    const int tx  = t & 15;
    const int ty  = t >> 4;
    const int q0  = blockIdx.x * ABM;
    const int bh  = blockIdx.y;
    const int b   = bh >> 3;
    const int h   = bh & 7;

    const float qscale = rsqrtf((float)HD_);

    // Load Q tile transposed + pre-scaled. 2048 float4 total, 8 per thread.
    #pragma unroll
    for (int i = 0; i < 8; i++) {
        int id  = t + i * 256;       // 0..2047
        int row = id >> 5;           // 0..63
        int d4  = id & 31;           // 0..31
        float4 v = *(const float4*)&qkv[((long)(b * S_ + q0 + row) * (3 * D_)) + h * HD_ + d4 * 4];
        Qt[(d4 * 4 + 0) * ABM + row] = v.x * qscale;
        Qt[(d4 * 4 + 1) * ABM + row] = v.y * qscale;
        Qt[(d4 * 4 + 2) * ABM + row] = v.z * qscale;
        Qt[(d4 * 4 + 3) * ABM + row] = v.w * qscale;
    }
    if (t < ABM) {
        rmax[t] = -1e30f;
        rsum[t] = 0.0f;
    }

    float acc[4][8];
    #pragma unroll
    for (int i = 0; i < 4; i++)
        #pragma unroll
        for (int j = 0; j < 8; j++) acc[i][j] = 0.0f;

    for (int kt = 0; kt < S_ / ABN; kt++) {
        __syncthreads();  // protect KV from previous iteration's readers

        // Load K tile transposed: Kt[d][n]
        #pragma unroll
        for (int i = 0; i < 8; i++) {
            int id = t + i * 256;
            int kl = id >> 5;
            int d4 = id & 31;
            float4 v = *(const float4*)&qkv[((long)(b * S_ + kt * ABN + kl) * (3 * D_)) + D_ + h * HD_ + d4 * 4];
            KV[(d4 * 4 + 0) * ABN + kl] = v.x;
            KV[(d4 * 4 + 1) * ABN + kl] = v.y;
            KV[(d4 * 4 + 2) * ABN + kl] = v.z;
            KV[(d4 * 4 + 3) * ABN + kl] = v.w;
        }
        __syncthreads();

        // S tile [64][64]: thread computes 4x4 (rows ty*4.., cols tx*4..)
        float s[4][4];
        #pragma unroll
        for (int i = 0; i < 4; i++)
            #pragma unroll
            for (int j = 0; j < 4; j++) s[i][j] = 0.0f;

        for (int k = 0; k < HD_; k++) {
            float4 a = *(const float4*)&Qt[k * ABM + ty * 4];
            float4 bb = *(const float4*)&KV[k * ABN + tx * 4];
            float av[4] = {a.x, a.y, a.z, a.w};
            float bv[4] = {bb.x, bb.y, bb.z, bb.w};
            #pragma unroll
            for (int i = 0; i < 4; i++)
                #pragma unroll
                for (int j = 0; j < 4; j++)
                    s[i][j] = fmaf(av[i], bv[j], s[i][j]);
        }

        // Mask + additive mask, write to Ss
        #pragma unroll
        for (int i = 0; i < 4; i++) {
            int rg = q0 + ty * 4 + i;
            #pragma unroll
            for (int j = 0; j < 4; j++) {
                int cg = kt * ABN + tx * 4 + j;
                bool ok = (rg < PREFIX_LEN) ? (cg < PREFIX_LEN) : (cg <= rg);
                float val = (ok ? s[i][j] : MASKED_BIAS) + amask[b * S_ + cg];
                Ss[(ty * 4 + i) * SS_LD + tx * 4 + j] = val;
            }
        }
        __syncthreads();

        // Phase A: per-row running max + rescale factor (64 threads)
        if (t < ABM) {
            float mold = rmax[t];
            float mnew = mold;
            #pragma unroll 8
            for (int c = 0; c < ABN; c++)
                mnew = fmaxf(mnew, Ss[t * SS_LD + c]);
            rscale[t] = __expf(mold - mnew);
            rmax[t]   = mnew;
        }
        __syncthreads();

        // Phase B: exp in place (all threads), rescale accumulators, load V
        #pragma unroll
        for (int i = 0; i < 16; i++) {
            int e   = t + i * 256;    // 0..4095
            int row = e >> 6;
            int col = e & 63;
            Ss[row * SS_LD + col] = __expf(Ss[row * SS_LD + col] - rmax[row]);
        }
        {
            float rs[4];
            #pragma unroll
            for (int i = 0; i < 4; i++) rs[i] = rscale[ty * 4 + i];
            #pragma unroll
            for (int i = 0; i < 4; i++)
                #pragma unroll
                for (int j = 0; j < 8; j++) acc[i][j] *= rs[i];
        }
        // V into KV as Vs[n][d] (K no longer needed)
        #pragma unroll
        for (int i = 0; i < 8; i++) {
            int id = t + i * 256;
            int kl = id >> 5;
            int d4 = id & 31;
            float4 v = *(const float4*)&qkv[((long)(b * S_ + kt * ABN + kl) * (3 * D_)) + 2 * D_ + h * HD_ + d4 * 4];
            *(float4*)&KV[kl * HD_ + d4 * 4] = v;
        }
        __syncthreads();

        // Phase C: row-sum update (first 64 threads), then AV for all
        if (t < ABM) {
            float ssum = 0.0f;
            #pragma unroll 8
            for (int c = 0; c < ABN; c++) ssum += Ss[t * SS_LD + c];
            rsum[t] = rsum[t] * rscale[t] + ssum;
        }

        // O[64][128] += P[64][64] @ V[64][128]; thread: rows ty*4.., cols tx*8..
        for (int n = 0; n < ABN; n++) {
            float p[4];
            #pragma unroll
            for (int i = 0; i < 4; i++) p[i] = Ss[(ty * 4 + i) * SS_LD + n];
            float4 v0 = *(const float4*)&KV[n * HD_ + tx * 8];
            float4 v1 = *(const float4*)&KV[n * HD_ + tx * 8 + 4];
            float v[8] = {v0.x, v0.y, v0.z, v0.w, v1.x, v1.y, v1.z, v1.w};
            #pragma unroll
            for (int i = 0; i < 4; i++)
                #pragma unroll
                for (int j = 0; j < 8; j++)
                    acc[i][j] = fmaf(p[i], v[j], acc[i][j]);
        }
    }

    __syncthreads();
    // Epilogue: divide by row sums, write merged-head layout [B,S,D]
    #pragma unroll
    for (int i = 0; i < 4; i++) {
        const int row = ty * 4 + i;
        const float inv = 1.0f / rsum[row];
        float4 o0, o1;
        o0.x = acc[i][0] * inv; o0.y = acc[i][1] * inv;
        o0.z = acc[i][2] * inv; o0.w = acc[i][3] * inv;
        o1.x = acc[i][4] * inv; o1.y = acc[i][5] * inv;
        o1.z = acc[i][6] * inv; o1.w = acc[i][7] * inv;
        long base = (long)(b * S_ + q0 + row) * D_ + h * HD_ + tx * 8;
        *(float4*)&aout[base]     = o0;
        *(float4*)&aout[base + 4] = o1;
    }
}

// ---------------------------------------------------------------------------
extern "C" void kernel_launch(void* const* d_in, const int* in_sizes, int n_in,
                              void* d_out, int out_size)
{
    const float* x      = (const float*)d_in[0];
    const float* amask  = (const float*)d_in[1];
    const float* W_attn = (const float*)d_in[2];
    const float* b_attn = (const float*)d_in[3];
    const float* W_proj = (const float*)d_in[4];
    const float* b_proj = (const float*)d_in[5];
    float* out = (float*)d_out;

    float* qkv;  cudaGetSymbolAddress((void**)&qkv,  g_qkv);
    float* attn; cudaGetSymbolAddress((void**)&attn, g_attn);

    cudaFuncSetAttribute(attn_kernel,
                         cudaFuncAttributeMaxDynamicSharedMemorySize,
                         ATTN_SMEM_BYTES);

    const int M = B_ * S_;   // 8192

    // 1) QKV GEMM: [8192,1024] @ [1024,3072] + bias
    {
        dim3 grid((3 * D_) / GBN, M / GBM);
        sgemm_bias<<<grid, 256>>>(x, W_attn, b_attn, qkv, M, 3 * D_, D_);
    }

    // 2) Fused attention
    {
        dim3 grid(S_ / ABM, B_ * H_);
        attn_kernel<<<grid, 256, ATTN_SMEM_BYTES>>>(qkv, amask, attn);
    }

    // 3) Output projection: [8192,1024] @ [1024,1024] + bias
    {
        dim3 grid(D_ / GBN, M / GBM);
        sgemm_bias<<<grid, 256>>>(attn, W_proj, b_proj, out, M, D_, D_);
    }
}

// round 3
// speedup vs baseline: 1.4904x; 1.4904x over previous
#include <cuda_runtime.h>
#include <math.h>
#include <stdint.h>

// Problem constants
#define B_   8
#define S_   1024
#define D_   1024
#define H_   8
#define HD_  128
#define PREFIX_LEN 77
#define MASKED_BIAS -10000.0f

// Scratch (no cudaMalloc allowed)
__device__ float g_qkv[B_ * S_ * 3 * D_];   // [B,S,3D]  96 MB
__device__ float g_attn[B_ * S_ * D_];      // [B,S,D]   32 MB

// ===========================================================================
// cp.async helpers
// ===========================================================================
__device__ __forceinline__ uint32_t s2u(const void* p) {
    return (uint32_t)__cvta_generic_to_shared((void*)p);
}
#define CP_ASYNC16(dst_u32, src_ptr) \
    asm volatile("cp.async.cg.shared.global [%0], [%1], 16;" \
                 :: "r"(dst_u32), "l"(src_ptr))
#define CP_COMMIT() asm volatile("cp.async.commit_group;" ::: "memory")
#define CP_WAIT2()  asm volatile("cp.async.wait_group 2;"  ::: "memory")

__device__ __forceinline__ uint32_t f2tf32(float v) {
    uint32_t r;
    asm("cvt.rna.tf32.f32 %0, %1;" : "=r"(r) : "f"(v));
    return r;
}

// ===========================================================================
// TF32 mma.sync GEMM: C[M,N] = A[M,K=1024] @ B[1024,N] + bias[N]
// CTA 128x128, BK=16, 8 warps (2x4), warp tile 64x32, 4-stage cp.async.
// ===========================================================================
#define BMg 128
#define BNg 128
#define BKg 16
#define KKg 1024
#define NCHg (KKg / BKg)          // 64
#define SA 20                     // As row stride (floats), conflict-free
#define SB 136                    // Bs row stride (floats), conflict-free
#define A_STG (BMg * SA)          // 2560 floats
#define B_STG (BKg * SB)          // 2176 floats
#define STG_FLOATS (A_STG + B_STG)
#define GEMM_SMEM (4 * STG_FLOATS * 4)   // 75776 bytes

__global__ __launch_bounds__(256, 2) void gemm_mma_tf32(
    const float* __restrict__ A, const float* __restrict__ Bw,
    const float* __restrict__ bias, float* __restrict__ C, int N)
{
    extern __shared__ float smf[];
    const uint32_t smem_u = s2u(smf);

    const int t    = threadIdx.x;
    const int wid  = t >> 5;
    const int lane = t & 31;
    const int g    = lane >> 2;     // 0..7
    const int tq   = lane & 3;      // 0..3
    const int wm   = wid >> 2;      // 0..1  (M warp)
    const int wn   = wid & 3;       // 0..3  (N warp)
    const int m0   = blockIdx.y * BMg;
    const int n0   = blockIdx.x * BNg;

    // ---- async chunk loader: 4 cp.asyncs per thread ----
    auto load_chunk = [&](int ch, int stg) {
        const int k0 = ch * BKg;
        const uint32_t base = smem_u + (uint32_t)(stg * STG_FLOATS) * 4u;
        // A tile: 128x16 -> 512 float4
        #pragma unroll
        for (int i = 0; i < 2; i++) {
            int idx = t + i * 256;          // 0..511
            int r = idx >> 2, c = (idx & 3) * 4;
            uint32_t dst = base + (uint32_t)(r * SA + c) * 4u;
            const float* src = A + (long)(m0 + r) * KKg + k0 + c;
            CP_ASYNC16(dst, src);
        }
        // B tile: 16x128 -> 512 float4
        #pragma unroll
        for (int i = 0; i < 2; i++) {
            int idx = t + i * 256;
            int r = idx >> 5, c = (idx & 31) * 4;
            uint32_t dst = base + (uint32_t)(A_STG + r * SB + c) * 4u;
            const float* src = Bw + (long)(k0 + r) * N + n0 + c;
            CP_ASYNC16(dst, src);
        }
    };

    // prologue: chunks 0..2
    #pragma unroll
    for (int c = 0; c < 3; c++) { load_chunk(c, c); CP_COMMIT(); }

    float acc[4][4][4];
    #pragma unroll
    for (int mt = 0; mt < 4; mt++)
        #pragma unroll
        for (int nt = 0; nt < 4; nt++)
            #pragma unroll
            for (int r = 0; r < 4; r++) acc[mt][nt][r] = 0.0f;

    for (int i = 0; i < NCHg; i++) {
        CP_WAIT2();
        __syncthreads();

        if (i + 3 < NCHg) load_chunk(i + 3, (i + 3) & 3);
        CP_COMMIT();

        const float* as = smf + (i & 3) * STG_FLOATS;
        const float* bs = as + A_STG;

        #pragma unroll
        for (int ks = 0; ks < 2; ks++) {
            uint32_t af[4][4], bf[4][2];
            #pragma unroll
            for (int mt = 0; mt < 4; mt++) {
                const int rb = wm * 64 + mt * 16;
                const int kc = ks * 8 + tq;
                af[mt][0] = f2tf32(as[(rb + g) * SA + kc]);
                af[mt][1] = f2tf32(as[(rb + g + 8) * SA + kc]);
                af[mt][2] = f2tf32(as[(rb + g) * SA + kc + 4]);
                af[mt][3] = f2tf32(as[(rb + g + 8) * SA + kc + 4]);
            }
            #pragma unroll
            for (int nt = 0; nt < 4; nt++) {
                const int nc = wn * 32 + nt * 8 + g;
                bf[nt][0] = f2tf32(bs[(ks * 8 + tq) * SB + nc]);
                bf[nt][1] = f2tf32(bs[(ks * 8 + tq + 4) * SB + nc]);
            }
            #pragma unroll
            for (int mt = 0; mt < 4; mt++)
                #pragma unroll
                for (int nt = 0; nt < 4; nt++) {
                    asm volatile(
                        "mma.sync.aligned.m16n8k8.row.col.f32.tf32.tf32.f32 "
                        "{%0,%1,%2,%3}, {%4,%5,%6,%7}, {%8,%9}, {%0,%1,%2,%3};"
                        : "+f"(acc[mt][nt][0]), "+f"(acc[mt][nt][1]),
                          "+f"(acc[mt][nt][2]), "+f"(acc[mt][nt][3])
                        : "r"(af[mt][0]), "r"(af[mt][1]),
                          "r"(af[mt][2]), "r"(af[mt][3]),
                          "r"(bf[nt][0]), "r"(bf[nt][1]));
                }
        }
    }

    // ---- epilogue: direct global stores (float2) + bias ----
    #pragma unroll
    for (int nt = 0; nt < 4; nt++) {
        const int col = n0 + wn * 32 + nt * 8 + tq * 2;
        const float bx = bias[col];
        const float by = bias[col + 1];
        #pragma unroll
        for (int mt = 0; mt < 4; mt++) {
            const int row = m0 + wm * 64 + mt * 16 + g;
            float2 v0 = make_float2(acc[mt][nt][0] + bx, acc[mt][nt][1] + by);
            float2 v1 = make_float2(acc[mt][nt][2] + bx, acc[mt][nt][3] + by);
            *(float2*)&C[(long)row * N + col]       = v0;
            *(float2*)&C[(long)(row + 8) * N + col] = v1;
        }
    }
}

// ===========================================================================
// Fused flash attention (fp32) — unchanged.
// ===========================================================================
#define ABM 64
#define ABN 64
#define SS_LD 65
#define ATTN_SMEM_FLOATS (HD_*ABM + HD_*ABN + ABM*SS_LD + 3*ABM)
#define ATTN_SMEM_BYTES  (ATTN_SMEM_FLOATS * 4)

__global__ __launch_bounds__(256) void attn_kernel(
    const float* __restrict__ qkv,
    const float* __restrict__ amask,
    float* __restrict__ aout)
{
    extern __shared__ float sm[];
    float* Qt     = sm;
    float* KV     = Qt + HD_ * ABM;
    float* Ss     = KV + HD_ * ABN;
    float* rmax   = Ss + ABM * SS_LD;
    float* rsum   = rmax + ABM;
    float* rscale = rsum + ABM;

    const int t   = threadIdx.x;
    const int tx  = t & 15;
    const int ty  = t >> 4;
    const int q0  = blockIdx.x * ABM;
    const int bh  = blockIdx.y;
    const int b   = bh >> 3;
    const int h   = bh & 7;

    const float qscale = rsqrtf((float)HD_);

    #pragma unroll
    for (int i = 0; i < 8; i++) {
        int id  = t + i * 256;
        int row = id >> 5;
        int d4  = id & 31;
        float4 v = *(const float4*)&qkv[((long)(b * S_ + q0 + row) * (3 * D_)) + h * HD_ + d4 * 4];
        Qt[(d4 * 4 + 0) * ABM + row] = v.x * qscale;
        Qt[(d4 * 4 + 1) * ABM + row] = v.y * qscale;
        Qt[(d4 * 4 + 2) * ABM + row] = v.z * qscale;
        Qt[(d4 * 4 + 3) * ABM + row] = v.w * qscale;
    }
    if (t < ABM) { rmax[t] = -1e30f; rsum[t] = 0.0f; }

    float acc[4][8];
    #pragma unroll
    for (int i = 0; i < 4; i++)
        #pragma unroll
        for (int j = 0; j < 8; j++) acc[i][j] = 0.0f;

    for (int kt = 0; kt < S_ / ABN; kt++) {
        __syncthreads();

        #pragma unroll
        for (int i = 0; i < 8; i++) {
            int id = t + i * 256;
            int kl = id >> 5;
            int d4 = id & 31;
            float4 v = *(const float4*)&qkv[((long)(b * S_ + kt * ABN + kl) * (3 * D_)) + D_ + h * HD_ + d4 * 4];
            KV[(d4 * 4 + 0) * ABN + kl] = v.x;
            KV[(d4 * 4 + 1) * ABN + kl] = v.y;
            KV[(d4 * 4 + 2) * ABN + kl] = v.z;
            KV[(d4 * 4 + 3) * ABN + kl] = v.w;
        }
        __syncthreads();

        float s[4][4];
        #pragma unroll
        for (int i = 0; i < 4; i++)
            #pragma unroll
            for (int j = 0; j < 4; j++) s[i][j] = 0.0f;

        for (int k = 0; k < HD_; k++) {
            float4 a  = *(const float4*)&Qt[k * ABM + ty * 4];
            float4 bb = *(const float4*)&KV[k * ABN + tx * 4];
            float av[4] = {a.x, a.y, a.z, a.w};
            float bv[4] = {bb.x, bb.y, bb.z, bb.w};
            #pragma unroll
            for (int i = 0; i < 4; i++)
                #pragma unroll
                for (int j = 0; j < 4; j++)
                    s[i][j] = fmaf(av[i], bv[j], s[i][j]);
        }

        #pragma unroll
        for (int i = 0; i < 4; i++) {
            int rg = q0 + ty * 4 + i;
            #pragma unroll
            for (int j = 0; j < 4; j++) {
                int cg = kt * ABN + tx * 4 + j;
                bool ok = (rg < PREFIX_LEN) ? (cg < PREFIX_LEN) : (cg <= rg);
                float val = (ok ? s[i][j] : MASKED_BIAS) + amask[b * S_ + cg];
                Ss[(ty * 4 + i) * SS_LD + tx * 4 + j] = val;
            }
        }
        __syncthreads();

        if (t < ABM) {
            float mold = rmax[t];
            float mnew = mold;
            #pragma unroll 8
            for (int c = 0; c < ABN; c++)
                mnew = fmaxf(mnew, Ss[t * SS_LD + c]);
            rscale[t] = __expf(mold - mnew);
            rmax[t]   = mnew;
        }
        __syncthreads();

        #pragma unroll
        for (int i = 0; i < 16; i++) {
            int e   = t + i * 256;
            int row = e >> 6;
            int col = e & 63;
            Ss[row * SS_LD + col] = __expf(Ss[row * SS_LD + col] - rmax[row]);
        }
        {
            float rs[4];
            #pragma unroll
            for (int i = 0; i < 4; i++) rs[i] = rscale[ty * 4 + i];
            #pragma unroll
            for (int i = 0; i < 4; i++)
                #pragma unroll
                for (int j = 0; j < 8; j++) acc[i][j] *= rs[i];
        }
        #pragma unroll
        for (int i = 0; i < 8; i++) {
            int id = t + i * 256;
            int kl = id >> 5;
            int d4 = id & 31;
            float4 v = *(const float4*)&qkv[((long)(b * S_ + kt * ABN + kl) * (3 * D_)) + 2 * D_ + h * HD_ + d4 * 4];
            *(float4*)&KV[kl * HD_ + d4 * 4] = v;
        }
        __syncthreads();

        if (t < ABM) {
            float ssum = 0.0f;
            #pragma unroll 8
            for (int c = 0; c < ABN; c++) ssum += Ss[t * SS_LD + c];
            rsum[t] = rsum[t] * rscale[t] + ssum;
        }

        for (int n = 0; n < ABN; n++) {
            float p[4];
            #pragma unroll
            for (int i = 0; i < 4; i++) p[i] = Ss[(ty * 4 + i) * SS_LD + n];
            float4 v0 = *(const float4*)&KV[n * HD_ + tx * 8];
            float4 v1 = *(const float4*)&KV[n * HD_ + tx * 8 + 4];
            float v[8] = {v0.x, v0.y, v0.z, v0.w, v1.x, v1.y, v1.z, v1.w};
            #pragma unroll
            for (int i = 0; i < 4; i++)
                #pragma unroll
                for (int j = 0; j < 8; j++)
                    acc[i][j] = fmaf(p[i], v[j], acc[i][j]);
        }
    }

    __syncthreads();
    #pragma unroll
    for (int i = 0; i < 4; i++) {
        const int row = ty * 4 + i;
        const float inv = 1.0f / rsum[row];
        float4 o0, o1;
        o0.x = acc[i][0] * inv; o0.y = acc[i][1] * inv;
        o0.z = acc[i][2] * inv; o0.w = acc[i][3] * inv;
        o1.x = acc[i][4] * inv; o1.y = acc[i][5] * inv;
        o1.z = acc[i][6] * inv; o1.w = acc[i][7] * inv;
        long base = (long)(b * S_ + q0 + row) * D_ + h * HD_ + tx * 8;
        *(float4*)&aout[base]     = o0;
        *(float4*)&aout[base + 4] = o1;
    }
}

// ===========================================================================
extern "C" void kernel_launch(void* const* d_in, const int* in_sizes, int n_in,
                              void* d_out, int out_size)
{
    const float* x      = (const float*)d_in[0];
    const float* amask  = (const float*)d_in[1];
    const float* W_attn = (const float*)d_in[2];
    const float* b_attn = (const float*)d_in[3];
    const float* W_proj = (const float*)d_in[4];
    const float* b_proj = (const float*)d_in[5];
    float* out = (float*)d_out;

    float* qkv;  cudaGetSymbolAddress((void**)&qkv,  g_qkv);
    float* attn; cudaGetSymbolAddress((void**)&attn, g_attn);

    cudaFuncSetAttribute(gemm_mma_tf32,
                         cudaFuncAttributeMaxDynamicSharedMemorySize, GEMM_SMEM);
    cudaFuncSetAttribute(attn_kernel,
                         cudaFuncAttributeMaxDynamicSharedMemorySize, ATTN_SMEM_BYTES);

    const int M = B_ * S_;   // 8192

    // 1) QKV GEMM (tensor core TF32): [8192,1024] @ [1024,3072] + bias
    {
        dim3 grid((3 * D_) / BNg, M / BMg);
        gemm_mma_tf32<<<grid, 256, GEMM_SMEM>>>(x, W_attn, b_attn, qkv, 3 * D_);
    }

    // 2) Fused attention
    {
        dim3 grid(S_ / ABM, B_ * H_);
        attn_kernel<<<grid, 256, ATTN_SMEM_BYTES>>>(qkv, amask, attn);
    }

    // 3) Output projection (tensor core TF32): [8192,1024] @ [1024,1024] + bias
    {
        dim3 grid(D_ / BNg, M / BMg);
        gemm_mma_tf32<<<grid, 256, GEMM_SMEM>>>(attn, W_proj, b_proj, out, D_);
    }
}

// round 4
// speedup vs baseline: 4.3016x; 2.8862x over previous
#include <cuda_runtime.h>
#include <math.h>
#include <stdint.h>

// Problem constants
#define B_   8
#define S_   1024
#define D_   1024
#define H_   8
#define HD_  128
#define PREFIX_LEN 77
#define MASKED_BIAS -10000.0f

// Scratch (no cudaMalloc allowed)
__device__ float g_qkv[B_ * S_ * 3 * D_];   // [B,S,3D]  96 MB
__device__ float g_attn[B_ * S_ * D_];      // [B,S,D]   32 MB

// ===========================================================================
// helpers
// ===========================================================================
__device__ __forceinline__ uint32_t s2u(const void* p) {
    return (uint32_t)__cvta_generic_to_shared((void*)p);
}
#define CP_ASYNC16(dst_u32, src_ptr) \
    asm volatile("cp.async.cg.shared.global [%0], [%1], 16;" \
                 :: "r"(dst_u32), "l"(src_ptr))
#define CP_COMMIT() asm volatile("cp.async.commit_group;" ::: "memory")
#define CP_WAIT2()  asm volatile("cp.async.wait_group 2;"  ::: "memory")

__device__ __forceinline__ uint32_t f2tf32(float v) {
    uint32_t r;
    asm("cvt.rna.tf32.f32 %0, %1;" : "=r"(r) : "f"(v));
    return r;
}

#define MMA_TF32(d, a0, a1, a2, a3, b0, b1) \
    asm volatile( \
        "mma.sync.aligned.m16n8k8.row.col.f32.tf32.tf32.f32 " \
        "{%0,%1,%2,%3}, {%4,%5,%6,%7}, {%8,%9}, {%0,%1,%2,%3};" \
        : "+f"((d)[0]), "+f"((d)[1]), "+f"((d)[2]), "+f"((d)[3]) \
        : "r"(a0), "r"(a1), "r"(a2), "r"(a3), "r"(b0), "r"(b1))

// ===========================================================================
// TF32 mma.sync GEMM: C[M,N] = A[M,K=1024] @ B[1024,N] + bias[N]
// (unchanged from round 3 — 365us QKV, tensor=47%)
// ===========================================================================
#define BMg 128
#define BNg 128
#define BKg 16
#define KKg 1024
#define NCHg (KKg / BKg)
#define SA 20
#define SB 136
#define A_STG (BMg * SA)
#define B_STG (BKg * SB)
#define STG_FLOATS (A_STG + B_STG)
#define GEMM_SMEM (4 * STG_FLOATS * 4)

__global__ __launch_bounds__(256, 2) void gemm_mma_tf32(
    const float* __restrict__ A, const float* __restrict__ Bw,
    const float* __restrict__ bias, float* __restrict__ C, int N)
{
    extern __shared__ float smf[];
    const uint32_t smem_u = s2u(smf);

    const int t    = threadIdx.x;
    const int wid  = t >> 5;
    const int lane = t & 31;
    const int g    = lane >> 2;
    const int tq   = lane & 3;
    const int wm   = wid >> 2;
    const int wn   = wid & 3;
    const int m0   = blockIdx.y * BMg;
    const int n0   = blockIdx.x * BNg;

    auto load_chunk = [&](int ch, int stg) {
        const int k0 = ch * BKg;
        const uint32_t base = smem_u + (uint32_t)(stg * STG_FLOATS) * 4u;
        #pragma unroll
        for (int i = 0; i < 2; i++) {
            int idx = t + i * 256;
            int r = idx >> 2, c = (idx & 3) * 4;
            uint32_t dst = base + (uint32_t)(r * SA + c) * 4u;
            const float* src = A + (long)(m0 + r) * KKg + k0 + c;
            CP_ASYNC16(dst, src);
        }
        #pragma unroll
        for (int i = 0; i < 2; i++) {
            int idx = t + i * 256;
            int r = idx >> 5, c = (idx & 31) * 4;
            uint32_t dst = base + (uint32_t)(A_STG + r * SB + c) * 4u;
            const float* src = Bw + (long)(k0 + r) * N + n0 + c;
            CP_ASYNC16(dst, src);
        }
    };

    #pragma unroll
    for (int c = 0; c < 3; c++) { load_chunk(c, c); CP_COMMIT(); }

    float acc[4][4][4];
    #pragma unroll
    for (int mt = 0; mt < 4; mt++)
        #pragma unroll
        for (int nt = 0; nt < 4; nt++)
            #pragma unroll
            for (int r = 0; r < 4; r++) acc[mt][nt][r] = 0.0f;

    for (int i = 0; i < NCHg; i++) {
        CP_WAIT2();
        __syncthreads();

        if (i + 3 < NCHg) load_chunk(i + 3, (i + 3) & 3);
        CP_COMMIT();

        const float* as = smf + (i & 3) * STG_FLOATS;
        const float* bs = as + A_STG;

        #pragma unroll
        for (int ks = 0; ks < 2; ks++) {
            uint32_t af[4][4], bf[4][2];
            #pragma unroll
            for (int mt = 0; mt < 4; mt++) {
                const int rb = wm * 64 + mt * 16;
                const int kc = ks * 8 + tq;
                af[mt][0] = f2tf32(as[(rb + g) * SA + kc]);
                af[mt][1] = f2tf32(as[(rb + g + 8) * SA + kc]);
                af[mt][2] = f2tf32(as[(rb + g) * SA + kc + 4]);
                af[mt][3] = f2tf32(as[(rb + g + 8) * SA + kc + 4]);
            }
            #pragma unroll
            for (int nt = 0; nt < 4; nt++) {
                const int nc = wn * 32 + nt * 8 + g;
                bf[nt][0] = f2tf32(bs[(ks * 8 + tq) * SB + nc]);
                bf[nt][1] = f2tf32(bs[(ks * 8 + tq + 4) * SB + nc]);
            }
            #pragma unroll
            for (int mt = 0; mt < 4; mt++)
                #pragma unroll
                for (int nt = 0; nt < 4; nt++)
                    MMA_TF32(acc[mt][nt], af[mt][0], af[mt][1], af[mt][2],
                             af[mt][3], bf[nt][0], bf[nt][1]);
        }
    }

    #pragma unroll
    for (int nt = 0; nt < 4; nt++) {
        const int col = n0 + wn * 32 + nt * 8 + tq * 2;
        const float bx = bias[col];
        const float by = bias[col + 1];
        #pragma unroll
        for (int mt = 0; mt < 4; mt++) {
            const int row = m0 + wm * 64 + mt * 16 + g;
            float2 v0 = make_float2(acc[mt][nt][0] + bx, acc[mt][nt][1] + by);
            float2 v1 = make_float2(acc[mt][nt][2] + bx, acc[mt][nt][3] + by);
            *(float2*)&C[(long)row * N + col]       = v0;
            *(float2*)&C[(long)(row + 8) * N + col] = v1;
        }
    }
}

// ===========================================================================
// Tensor-core flash attention (TF32 mma).
// Grid: (S/128, B*H). 256 threads (8 warps). Warp w owns query rows w*16..+15.
// Key tiles of 64, causal tile skipping, online softmax in registers.
// ===========================================================================
#define QBM 128
#define QBN 64
#define QKS 132    // Qs/Ks row stride (floats): banks 4g+tq distinct
#define VST 136    // Vs row stride: banks 8tq+g distinct
#define PST 68     // Ps row stride: banks 4g+tq distinct

#define Q_FLOATS (QBM * QKS)
#define K_FLOATS (QBN * QKS)
#define V_FLOATS (QBN * VST)
#define P_FLOATS (QBM * PST)
#define ATTN_SMEM ((Q_FLOATS + K_FLOATS + V_FLOATS + P_FLOATS) * 4)

__global__ __launch_bounds__(256, 1) void attn_mma(
    const float* __restrict__ qkv,      // [B,S,3D]
    const float* __restrict__ amask,    // [B,1,1,S]
    float* __restrict__ aout)           // [B,S,D]
{
    extern __shared__ float sm[];
    float* Qs = sm;
    float* Ks = Qs + Q_FLOATS;
    float* Vs = Ks + K_FLOATS;
    float* Ps = Vs + V_FLOATS;

    const int t    = threadIdx.x;
    const int wid  = t >> 5;
    const int lane = t & 31;
    const int g    = lane >> 2;   // 0..7
    const int tq   = lane & 3;    // 0..3
    const int q0   = blockIdx.x * QBM;
    const int bh   = blockIdx.y;
    const int b    = bh >> 3;
    const int h    = bh & 7;
    const int rb   = wid * 16;    // warp's query row base within tile

    const float qscale = rsqrtf((float)HD_);

    // ---- load Q tile [128][128] scaled ----
    #pragma unroll
    for (int i = 0; i < 16; i++) {
        int idx = t + i * 256;          // 0..4095
        int row = idx >> 5;
        int c4  = idx & 31;
        float4 v = *(const float4*)&qkv[(long)(b * S_ + q0 + row) * (3 * D_) + h * HD_ + c4 * 4];
        v.x *= qscale; v.y *= qscale; v.z *= qscale; v.w *= qscale;
        *(float4*)&Qs[row * QKS + c4 * 4] = v;
    }

    float o[16][4];
    #pragma unroll
    for (int nt = 0; nt < 16; nt++)
        #pragma unroll
        for (int r = 0; r < 4; r++) o[nt][r] = 0.0f;
    float m0 = -1e30f, m1 = -1e30f, l0 = 0.0f, l1 = 0.0f;

    const int row0 = q0 + rb + g;
    const int row1 = row0 + 8;
    const int nkt  = q0 / QBN + 2;     // causal tile limit

    for (int kt = 0; kt < nkt; kt++) {
        __syncthreads();   // protect Ks/Vs from previous iteration readers

        // ---- load K,V tiles [64][128] ----
        #pragma unroll
        for (int i = 0; i < 8; i++) {
            int idx = t + i * 256;      // 0..2047
            int row = idx >> 5;
            int c4  = idx & 31;
            long base = (long)(b * S_ + kt * QBN + row) * (3 * D_) + h * HD_ + c4 * 4;
            *(float4*)&Ks[row * QKS + c4 * 4] = *(const float4*)&qkv[base + D_];
            *(float4*)&Vs[row * VST + c4 * 4] = *(const float4*)&qkv[base + 2 * D_];
        }
        __syncthreads();

        // ---- S = Q @ K^T : warp tile 16x64 ----
        float sacc[8][4];
        #pragma unroll
        for (int nt = 0; nt < 8; nt++)
            #pragma unroll
            for (int r = 0; r < 4; r++) sacc[nt][r] = 0.0f;

        #pragma unroll
        for (int ks = 0; ks < 16; ks++) {
            const int kc = ks * 8 + tq;
            uint32_t a0 = f2tf32(Qs[(rb + g) * QKS + kc]);
            uint32_t a1 = f2tf32(Qs[(rb + g + 8) * QKS + kc]);
            uint32_t a2 = f2tf32(Qs[(rb + g) * QKS + kc + 4]);
            uint32_t a3 = f2tf32(Qs[(rb + g + 8) * QKS + kc + 4]);
            #pragma unroll
            for (int nt = 0; nt < 8; nt++) {
                uint32_t b0 = f2tf32(Ks[(nt * 8 + g) * QKS + kc]);
                uint32_t b1 = f2tf32(Ks[(nt * 8 + g) * QKS + kc + 4]);
                MMA_TF32(sacc[nt], a0, a1, a2, a3, b0, b1);
            }
        }

        // ---- mask + additive mask ----
        float mloc0 = -1e30f, mloc1 = -1e30f;
        #pragma unroll
        for (int nt = 0; nt < 8; nt++) {
            const int c0 = kt * QBN + nt * 8 + 2 * tq;
            const int c1 = c0 + 1;
            const float am0 = amask[b * S_ + c0];
            const float am1 = amask[b * S_ + c1];
            bool ok00 = (row0 < PREFIX_LEN) ? (c0 < PREFIX_LEN) : (c0 <= row0);
            bool ok01 = (row0 < PREFIX_LEN) ? (c1 < PREFIX_LEN) : (c1 <= row0);
            bool ok10 = (row1 < PREFIX_LEN) ? (c0 < PREFIX_LEN) : (c0 <= row1);
            bool ok11 = (row1 < PREFIX_LEN) ? (c1 < PREFIX_LEN) : (c1 <= row1);
            sacc[nt][0] = (ok00 ? sacc[nt][0] : MASKED_BIAS) + am0;
            sacc[nt][1] = (ok01 ? sacc[nt][1] : MASKED_BIAS) + am1;
            sacc[nt][2] = (ok10 ? sacc[nt][2] : MASKED_BIAS) + am0;
            sacc[nt][3] = (ok11 ? sacc[nt][3] : MASKED_BIAS) + am1;
            mloc0 = fmaxf(mloc0, fmaxf(sacc[nt][0], sacc[nt][1]));
            mloc1 = fmaxf(mloc1, fmaxf(sacc[nt][2], sacc[nt][3]));
        }
        // quad reduction (lanes g*4..g*4+3 share a row)
        mloc0 = fmaxf(mloc0, __shfl_xor_sync(0xFFFFFFFF, mloc0, 1));
        mloc0 = fmaxf(mloc0, __shfl_xor_sync(0xFFFFFFFF, mloc0, 2));
        mloc1 = fmaxf(mloc1, __shfl_xor_sync(0xFFFFFFFF, mloc1, 1));
        mloc1 = fmaxf(mloc1, __shfl_xor_sync(0xFFFFFFFF, mloc1, 2));

        const float mn0 = fmaxf(m0, mloc0);
        const float mn1 = fmaxf(m1, mloc1);
        const float sc0 = __expf(m0 - mn0);
        const float sc1 = __expf(m1 - mn1);
        m0 = mn0; m1 = mn1;

        float ls0 = 0.0f, ls1 = 0.0f;
        #pragma unroll
        for (int nt = 0; nt < 8; nt++) {
            sacc[nt][0] = __expf(sacc[nt][0] - mn0);
            sacc[nt][1] = __expf(sacc[nt][1] - mn0);
            sacc[nt][2] = __expf(sacc[nt][2] - mn1);
            sacc[nt][3] = __expf(sacc[nt][3] - mn1);
            ls0 += sacc[nt][0] + sacc[nt][1];
            ls1 += sacc[nt][2] + sacc[nt][3];
        }
        ls0 += __shfl_xor_sync(0xFFFFFFFF, ls0, 1);
        ls0 += __shfl_xor_sync(0xFFFFFFFF, ls0, 2);
        ls1 += __shfl_xor_sync(0xFFFFFFFF, ls1, 1);
        ls1 += __shfl_xor_sync(0xFFFFFFFF, ls1, 2);
        l0 = l0 * sc0 + ls0;
        l1 = l1 * sc1 + ls1;

        // rescale O
        #pragma unroll
        for (int nt = 0; nt < 16; nt++) {
            o[nt][0] *= sc0; o[nt][1] *= sc0;
            o[nt][2] *= sc1; o[nt][3] *= sc1;
        }

        // write P (warp-private rows; no sync needed before re-read)
        #pragma unroll
        for (int nt = 0; nt < 8; nt++) {
            *(float2*)&Ps[(rb + g) * PST + nt * 8 + 2 * tq]     = make_float2(sacc[nt][0], sacc[nt][1]);
            *(float2*)&Ps[(rb + g + 8) * PST + nt * 8 + 2 * tq] = make_float2(sacc[nt][2], sacc[nt][3]);
        }

        // ---- O += P @ V : warp tile 16x128, K=64 ----
        #pragma unroll
        for (int kk = 0; kk < 8; kk++) {
            const int kc = kk * 8 + tq;
            uint32_t a0 = f2tf32(Ps[(rb + g) * PST + kc]);
            uint32_t a1 = f2tf32(Ps[(rb + g + 8) * PST + kc]);
            uint32_t a2 = f2tf32(Ps[(rb + g) * PST + kc + 4]);
            uint32_t a3 = f2tf32(Ps[(rb + g + 8) * PST + kc + 4]);
            #pragma unroll
            for (int nt = 0; nt < 16; nt++) {
                uint32_t b0 = f2tf32(Vs[kc * VST + nt * 8 + g]);
                uint32_t b1 = f2tf32(Vs[(kc + 4) * VST + nt * 8 + g]);
                MMA_TF32(o[nt], a0, a1, a2, a3, b0, b1);
            }
        }
    }

    // ---- epilogue ----
    const float inv0 = 1.0f / l0;
    const float inv1 = 1.0f / l1;
    #pragma unroll
    for (int nt = 0; nt < 16; nt++) {
        const int col = h * HD_ + nt * 8 + 2 * tq;
        float2 v0 = make_float2(o[nt][0] * inv0, o[nt][1] * inv0);
        float2 v1 = make_float2(o[nt][2] * inv1, o[nt][3] * inv1);
        *(float2*)&aout[(long)(b * S_ + row0) * D_ + col] = v0;
        *(float2*)&aout[(long)(b * S_ + row1) * D_ + col] = v1;
    }
}

// ===========================================================================
extern "C" void kernel_launch(void* const* d_in, const int* in_sizes, int n_in,
                              void* d_out, int out_size)
{
    const float* x      = (const float*)d_in[0];
    const float* amask  = (const float*)d_in[1];
    const float* W_attn = (const float*)d_in[2];
    const float* b_attn = (const float*)d_in[3];
    const float* W_proj = (const float*)d_in[4];
    const float* b_proj = (const float*)d_in[5];
    float* out = (float*)d_out;

    float* qkv;  cudaGetSymbolAddress((void**)&qkv,  g_qkv);
    float* attn; cudaGetSymbolAddress((void**)&attn, g_attn);

    cudaFuncSetAttribute(gemm_mma_tf32,
                         cudaFuncAttributeMaxDynamicSharedMemorySize, GEMM_SMEM);
    cudaFuncSetAttribute(attn_mma,
                         cudaFuncAttributeMaxDynamicSharedMemorySize, ATTN_SMEM);

    const int M = B_ * S_;   // 8192

    // 1) QKV GEMM (tensor core TF32)
    {
        dim3 grid((3 * D_) / BNg, M / BMg);
        gemm_mma_tf32<<<grid, 256, GEMM_SMEM>>>(x, W_attn, b_attn, qkv, 3 * D_);
    }

    // 2) Tensor-core flash attention
    {
        dim3 grid(S_ / QBM, B_ * H_);
        attn_mma<<<grid, 256, ATTN_SMEM>>>(qkv, amask, attn);
    }

    // 3) Output projection (tensor core TF32)
    {
        dim3 grid(D_ / BNg, M / BMg);
        gemm_mma_tf32<<<grid, 256, GEMM_SMEM>>>(attn, W_proj, b_proj, out, D_);
    }
}

// round 5
// speedup vs baseline: 8.6575x; 2.0126x over previous
#include <cuda_runtime.h>
#include <cuda_fp16.h>
#include <math.h>
#include <stdint.h>

// Problem constants
#define B_   8
#define S_   1024
#define D_   1024
#define H_   8
#define HD_  128
#define PREFIX_LEN 77
#define MASKED_BIAS -10000.0f

// Scratch (no cudaMalloc allowed)
__device__ __half g_xh[B_ * S_ * D_];          // x fp16           16 MB
__device__ __half g_wah[D_ * 3 * D_];          // W_attn fp16       6 MB
__device__ __half g_wph[D_ * D_];              // W_proj fp16       2 MB
__device__ __half g_qkv[B_ * S_ * 3 * D_];     // qkv fp16         48 MB
__device__ __half g_attn[B_ * S_ * D_];        // attn out fp16    16 MB

// ===========================================================================
// helpers
// ===========================================================================
__device__ __forceinline__ uint32_t s2u(const void* p) {
    return (uint32_t)__cvta_generic_to_shared((void*)p);
}
#define CP_ASYNC16(dst_u32, src_ptr) \
    asm volatile("cp.async.cg.shared.global [%0], [%1], 16;" \
                 :: "r"(dst_u32), "l"(src_ptr))
#define CP_COMMIT() asm volatile("cp.async.commit_group;" ::: "memory")
#define CP_WAIT2()  asm volatile("cp.async.wait_group 2;"  ::: "memory")

#define LDSM_X4(r0, r1, r2, r3, addr) \
    asm volatile("ldmatrix.sync.aligned.m8n8.x4.shared.b16 {%0,%1,%2,%3}, [%4];" \
        : "=r"(r0), "=r"(r1), "=r"(r2), "=r"(r3) : "r"(addr))
#define LDSM_X4_T(r0, r1, r2, r3, addr) \
    asm volatile("ldmatrix.sync.aligned.m8n8.x4.trans.shared.b16 {%0,%1,%2,%3}, [%4];" \
        : "=r"(r0), "=r"(r1), "=r"(r2), "=r"(r3) : "r"(addr))

#define MMA_F16(d, a0, a1, a2, a3, b0, b1) \
    asm volatile( \
        "mma.sync.aligned.m16n8k16.row.col.f32.f16.f16.f32 " \
        "{%0,%1,%2,%3}, {%4,%5,%6,%7}, {%8,%9}, {%0,%1,%2,%3};" \
        : "+f"((d)[0]), "+f"((d)[1]), "+f"((d)[2]), "+f"((d)[3]) \
        : "r"(a0), "r"(a1), "r"(a2), "r"(a3), "r"(b0), "r"(b1))

// ===========================================================================
// fp32 -> fp16 conversion prepass
// ===========================================================================
__global__ __launch_bounds__(256) void f2h_kernel(
    const float* __restrict__ src, __half* __restrict__ dst, int n4)
{
    int i = blockIdx.x * blockDim.x + threadIdx.x;
    if (i >= n4) return;
    float4 v = ((const float4*)src)[i];
    __half2* d2 = (__half2*)dst;
    d2[2 * i]     = __floats2half2_rn(v.x, v.y);
    d2[2 * i + 1] = __floats2half2_rn(v.z, v.w);
}

// ===========================================================================
// FP16 mma GEMM: C[M,N] = A[M,1024] @ B[1024,N] + bias[N]
// CTA 128x128, BK=32, 8 warps (2x4), warp tile 64x32, 4-stage cp.async,
// ldmatrix fragments. A smem stride 40 halves (80B), B stride 136 (272B):
// both give conflict-free ldmatrix phases.
// ===========================================================================
#define KKg 1024
#define BKg 32
#define NCHg (KKg / BKg)           // 32
#define SA_H 40
#define SB_H 136
#define A_BYTES (128 * SA_H * 2)   // 10240
#define B_BYTES (BKg * SB_H * 2)   // 8704
#define STAGE_BYTES (A_BYTES + B_BYTES)     // 18944
#define GEMM_SMEM (4 * STAGE_BYTES)         // 75776

template <bool OUT_HALF>
__global__ __launch_bounds__(256, 2) void gemm_mma_f16(
    const __half* __restrict__ A, const __half* __restrict__ Bw,
    const float* __restrict__ bias, void* __restrict__ Cv, int N)
{
    extern __shared__ char smraw[];
    const uint32_t su = s2u(smraw);

    const int t    = threadIdx.x;
    const int wid  = t >> 5;
    const int lane = t & 31;
    const int g    = lane >> 2;
    const int tq   = lane & 3;
    const int wm   = wid >> 2;      // 0..1
    const int wn   = wid & 3;       // 0..3
    const int m0   = blockIdx.y * 128;
    const int n0   = blockIdx.x * 128;

    const int l15  = lane & 15;
    const int l7   = lane & 7;
    const int hi8a = (lane & 16) ? 8 : 0;
    const int hi8b = (lane & 8)  ? 8 : 0;

    auto load_chunk = [&](int ch, int stg) {
        const int k0 = ch * BKg;
        const uint32_t base = su + (uint32_t)stg * STAGE_BYTES;
        #pragma unroll
        for (int i = 0; i < 2; i++) {          // A: 128x32 halves, 512 x 16B
            int idx = t + i * 256;
            int r = idx >> 2, c = idx & 3;
            uint32_t dst = base + (uint32_t)(r * (SA_H * 2) + c * 16);
            const __half* src = A + (long)(m0 + r) * KKg + k0 + c * 8;
            CP_ASYNC16(dst, src);
        }
        #pragma unroll
        for (int i = 0; i < 2; i++) {          // B: 32x128 halves, 512 x 16B
            int idx = t + i * 256;
            int r = idx >> 4, c = idx & 15;
            uint32_t dst = base + A_BYTES + (uint32_t)(r * (SB_H * 2) + c * 16);
            const __half* src = Bw + (long)(k0 + r) * N + n0 + c * 8;
            CP_ASYNC16(dst, src);
        }
    };

    #pragma unroll
    for (int c = 0; c < 3; c++) { load_chunk(c, c); CP_COMMIT(); }

    float acc[4][4][4];
    #pragma unroll
    for (int mt = 0; mt < 4; mt++)
        #pragma unroll
        for (int nt = 0; nt < 4; nt++)
            #pragma unroll
            for (int r = 0; r < 4; r++) acc[mt][nt][r] = 0.0f;

    for (int i = 0; i < NCHg; i++) {
        CP_WAIT2();
        __syncthreads();

        if (i + 3 < NCHg) load_chunk(i + 3, (i + 3) & 3);
        CP_COMMIT();

        const uint32_t sa = su + (uint32_t)(i & 3) * STAGE_BYTES;
        const uint32_t sb = sa + A_BYTES;

        #pragma unroll
        for (int ks = 0; ks < 2; ks++) {
            uint32_t af[4][4], bf[4][2];
            #pragma unroll
            for (int mt = 0; mt < 4; mt++) {
                uint32_t addr = sa + 2u * (uint32_t)(
                    (wm * 64 + mt * 16 + l15) * SA_H + ks * 16 + hi8a);
                LDSM_X4(af[mt][0], af[mt][1], af[mt][2], af[mt][3], addr);
            }
            #pragma unroll
            for (int np = 0; np < 2; np++) {
                uint32_t addr = sb + 2u * (uint32_t)(
                    (ks * 16 + l7 + hi8b) * SB_H + wn * 32 + np * 16 + hi8a);
                LDSM_X4_T(bf[2 * np][0], bf[2 * np][1],
                          bf[2 * np + 1][0], bf[2 * np + 1][1], addr);
            }
            #pragma unroll
            for (int mt = 0; mt < 4; mt++)
                #pragma unroll
                for (int nt = 0; nt < 4; nt++)
                    MMA_F16(acc[mt][nt], af[mt][0], af[mt][1], af[mt][2],
                            af[mt][3], bf[nt][0], bf[nt][1]);
        }
    }

    // ---- epilogue ----
    #pragma unroll
    for (int nt = 0; nt < 4; nt++) {
        const int col = n0 + wn * 32 + nt * 8 + tq * 2;
        const float bx = bias[col];
        const float by = bias[col + 1];
        #pragma unroll
        for (int mt = 0; mt < 4; mt++) {
            const int row = m0 + wm * 64 + mt * 16 + g;
            if (OUT_HALF) {
                __half* C = (__half*)Cv;
                *(__half2*)&C[(long)row * N + col] =
                    __floats2half2_rn(acc[mt][nt][0] + bx, acc[mt][nt][1] + by);
                *(__half2*)&C[(long)(row + 8) * N + col] =
                    __floats2half2_rn(acc[mt][nt][2] + bx, acc[mt][nt][3] + by);
            } else {
                float* C = (float*)Cv;
                *(float2*)&C[(long)row * N + col] =
                    make_float2(acc[mt][nt][0] + bx, acc[mt][nt][1] + by);
                *(float2*)&C[(long)(row + 8) * N + col] =
                    make_float2(acc[mt][nt][2] + bx, acc[mt][nt][3] + by);
            }
        }
    }
}

// ===========================================================================
// FP16 tensor-core flash attention.
// Grid: (S/128, B*H). 8 warps, warp = 16 query rows. Key tiles 64, causal
// tile skipping, fp32 softmax in registers, P staged fp16 in SMEM.
// ===========================================================================
#define QKS_H 136                  // Q/K/V smem row stride (halves)
#define PST_H 72                   // P smem row stride (halves)
#define Q_OFF 0
#define K_OFF (128 * QKS_H)                   // 17408
#define V_OFF (K_OFF + 64 * QKS_H)            // 26112
#define P_OFF (V_OFF + 64 * QKS_H)            // 34816
#define ATTN_SMEM ((P_OFF + 128 * PST_H) * 2) // 88064 bytes

__global__ __launch_bounds__(256, 1) void attn_mma_f16(
    const __half* __restrict__ qkv,     // [B,S,3D] fp16
    const float* __restrict__ amask,    // [B,1,1,S] fp32
    __half* __restrict__ aout)          // [B,S,D] fp16
{
    extern __shared__ __half smh[];
    const uint32_t su = s2u(smh);
    const uint32_t Qu = su + Q_OFF * 2;
    const uint32_t Ku = su + K_OFF * 2;
    const uint32_t Vu = su + V_OFF * 2;
    const uint32_t Pu = su + P_OFF * 2;

    const int t    = threadIdx.x;
    const int wid  = t >> 5;
    const int lane = t & 31;
    const int g    = lane >> 2;
    const int tq   = lane & 3;
    const int q0   = blockIdx.x * 128;
    const int bh   = blockIdx.y;
    const int b    = bh >> 3;
    const int h    = bh & 7;
    const int rb   = wid * 16;

    const int l15  = lane & 15;
    const int l7   = lane & 7;
    const int hi8a = (lane & 16) ? 8 : 0;
    const int hi8b = (lane & 8)  ? 8 : 0;

    const float qscale = rsqrtf((float)HD_);

    // ---- load Q tile [128][128] halves ----
    #pragma unroll
    for (int i = 0; i < 8; i++) {
        int idx = t + i * 256;          // 0..2047
        int row = idx >> 4;
        int c   = idx & 15;
        *(uint4*)&smh[Q_OFF + row * QKS_H + c * 8] =
            *(const uint4*)&qkv[(long)(b * S_ + q0 + row) * (3 * D_) + h * HD_ + c * 8];
    }

    float o[16][4];
    #pragma unroll
    for (int nt = 0; nt < 16; nt++)
        #pragma unroll
        for (int r = 0; r < 4; r++) o[nt][r] = 0.0f;
    float m0 = -1e30f, m1 = -1e30f, l0 = 0.0f, l1 = 0.0f;

    const int row0 = q0 + rb + g;
    const int row1 = row0 + 8;
    const int nkt  = q0 / 64 + 2;       // causal tile limit

    for (int kt = 0; kt < nkt; kt++) {
        __syncthreads();

        // ---- load K,V tiles [64][128] halves ----
        #pragma unroll
        for (int i = 0; i < 4; i++) {
            int idx = t + i * 256;       // 0..1023
            int row = idx >> 4;
            int c   = idx & 15;
            long base = (long)(b * S_ + kt * 64 + row) * (3 * D_) + h * HD_ + c * 8;
            *(uint4*)&smh[K_OFF + row * QKS_H + c * 8] = *(const uint4*)&qkv[base + D_];
            *(uint4*)&smh[V_OFF + row * QKS_H + c * 8] = *(const uint4*)&qkv[base + 2 * D_];
        }
        __syncthreads();

        // ---- S = Q @ K^T : warp tile 16x64 (8 n-tiles) ----
        float sacc[8][4];
        #pragma unroll
        for (int nt = 0; nt < 8; nt++)
            #pragma unroll
            for (int r = 0; r < 4; r++) sacc[nt][r] = 0.0f;

        #pragma unroll
        for (int ks = 0; ks < 8; ks++) {
            uint32_t a0, a1, a2, a3;
            LDSM_X4(a0, a1, a2, a3,
                    Qu + 2u * (uint32_t)((rb + l15) * QKS_H + ks * 16 + hi8a));
            #pragma unroll
            for (int np = 0; np < 4; np++) {
                uint32_t b0, b1, b2, b3;
                LDSM_X4(b0, b1, b2, b3,
                        Ku + 2u * (uint32_t)((np * 16 + l7 + hi8a) * QKS_H + ks * 16 + hi8b));
                MMA_F16(sacc[2 * np],     a0, a1, a2, a3, b0, b1);
                MMA_F16(sacc[2 * np + 1], a0, a1, a2, a3, b2, b3);
            }
        }

        // ---- scale + mask ----
        float mloc0 = -1e30f, mloc1 = -1e30f;
        #pragma unroll
        for (int nt = 0; nt < 8; nt++) {
            const int c0 = kt * 64 + nt * 8 + 2 * tq;
            const int c1 = c0 + 1;
            const float am0 = amask[b * S_ + c0];
            const float am1 = amask[b * S_ + c1];
            bool ok00 = (row0 < PREFIX_LEN) ? (c0 < PREFIX_LEN) : (c0 <= row0);
            bool ok01 = (row0 < PREFIX_LEN) ? (c1 < PREFIX_LEN) : (c1 <= row0);
            bool ok10 = (row1 < PREFIX_LEN) ? (c0 < PREFIX_LEN) : (c0 <= row1);
            bool ok11 = (row1 < PREFIX_LEN) ? (c1 < PREFIX_LEN) : (c1 <= row1);
            sacc[nt][0] = (ok00 ? sacc[nt][0] * qscale : MASKED_BIAS) + am0;
            sacc[nt][1] = (ok01 ? sacc[nt][1] * qscale : MASKED_BIAS) + am1;
            sacc[nt][2] = (ok10 ? sacc[nt][2] * qscale : MASKED_BIAS) + am0;
            sacc[nt][3] = (ok11 ? sacc[nt][3] * qscale : MASKED_BIAS) + am1;
            mloc0 = fmaxf(mloc0, fmaxf(sacc[nt][0], sacc[nt][1]));
            mloc1 = fmaxf(mloc1, fmaxf(sacc[nt][2], sacc[nt][3]));
        }
        mloc0 = fmaxf(mloc0, __shfl_xor_sync(0xFFFFFFFF, mloc0, 1));
        mloc0 = fmaxf(mloc0, __shfl_xor_sync(0xFFFFFFFF, mloc0, 2));
        mloc1 = fmaxf(mloc1, __shfl_xor_sync(0xFFFFFFFF, mloc1, 1));
        mloc1 = fmaxf(mloc1, __shfl_xor_sync(0xFFFFFFFF, mloc1, 2));

        const float mn0 = fmaxf(m0, mloc0);
        const float mn1 = fmaxf(m1, mloc1);
        const float sc0 = __expf(m0 - mn0);
        const float sc1 = __expf(m1 - mn1);
        m0 = mn0; m1 = mn1;

        float ls0 = 0.0f, ls1 = 0.0f;
        #pragma unroll
        for (int nt = 0; nt < 8; nt++) {
            sacc[nt][0] = __expf(sacc[nt][0] - mn0);
            sacc[nt][1] = __expf(sacc[nt][1] - mn0);
            sacc[nt][2] = __expf(sacc[nt][2] - mn1);
            sacc[nt][3] = __expf(sacc[nt][3] - mn1);
            ls0 += sacc[nt][0] + sacc[nt][1];
            ls1 += sacc[nt][2] + sacc[nt][3];
        }
        ls0 += __shfl_xor_sync(0xFFFFFFFF, ls0, 1);
        ls0 += __shfl_xor_sync(0xFFFFFFFF, ls0, 2);
        ls1 += __shfl_xor_sync(0xFFFFFFFF, ls1, 1);
        ls1 += __shfl_xor_sync(0xFFFFFFFF, ls1, 2);
        l0 = l0 * sc0 + ls0;
        l1 = l1 * sc1 + ls1;

        #pragma unroll
        for (int nt = 0; nt < 16; nt++) {
            o[nt][0] *= sc0; o[nt][1] *= sc0;
            o[nt][2] *= sc1; o[nt][3] *= sc1;
        }

        // ---- P -> SMEM fp16 (warp-private rows) ----
        #pragma unroll
        for (int nt = 0; nt < 8; nt++) {
            *(__half2*)&smh[P_OFF + (rb + g) * PST_H + nt * 8 + 2 * tq] =
                __floats2half2_rn(sacc[nt][0], sacc[nt][1]);
            *(__half2*)&smh[P_OFF + (rb + g + 8) * PST_H + nt * 8 + 2 * tq] =
                __floats2half2_rn(sacc[nt][2], sacc[nt][3]);
        }
        __syncwarp();

        // ---- O += P @ V : warp tile 16x128, K=64 ----
        #pragma unroll
        for (int kk = 0; kk < 4; kk++) {
            uint32_t a0, a1, a2, a3;
            LDSM_X4(a0, a1, a2, a3,
                    Pu + 2u * (uint32_t)((rb + l15) * PST_H + kk * 16 + hi8a));
            #pragma unroll
            for (int np = 0; np < 8; np++) {
                uint32_t b0, b1, b2, b3;
                LDSM_X4_T(b0, b1, b2, b3,
                          Vu + 2u * (uint32_t)((kk * 16 + l7 + hi8b) * QKS_H + np * 16 + hi8a));
                MMA_F16(o[2 * np],     a0, a1, a2, a3, b0, b1);
                MMA_F16(o[2 * np + 1], a0, a1, a2, a3, b2, b3);
            }
        }
    }

    // ---- epilogue ----
    const float inv0 = 1.0f / l0;
    const float inv1 = 1.0f / l1;
    #pragma unroll
    for (int nt = 0; nt < 16; nt++) {
        const int col = h * HD_ + nt * 8 + 2 * tq;
        *(__half2*)&aout[(long)(b * S_ + row0) * D_ + col] =
            __floats2half2_rn(o[nt][0] * inv0, o[nt][1] * inv0);
        *(__half2*)&aout[(long)(b * S_ + row1) * D_ + col] =
            __floats2half2_rn(o[nt][2] * inv1, o[nt][3] * inv1);
    }
}

// ===========================================================================
extern "C" void kernel_launch(void* const* d_in, const int* in_sizes, int n_in,
                              void* d_out, int out_size)
{
    const float* x      = (const float*)d_in[0];
    const float* amask  = (const float*)d_in[1];
    const float* W_attn = (const float*)d_in[2];
    const float* b_attn = (const float*)d_in[3];
    const float* W_proj = (const float*)d_in[4];
    const float* b_proj = (const float*)d_in[5];
    float* out = (float*)d_out;

    __half *xh, *wah, *wph, *qkv, *attn;
    cudaGetSymbolAddress((void**)&xh,   g_xh);
    cudaGetSymbolAddress((void**)&wah,  g_wah);
    cudaGetSymbolAddress((void**)&wph,  g_wph);
    cudaGetSymbolAddress((void**)&qkv,  g_qkv);
    cudaGetSymbolAddress((void**)&attn, g_attn);

    cudaFuncSetAttribute(gemm_mma_f16<true>,
                         cudaFuncAttributeMaxDynamicSharedMemorySize, GEMM_SMEM);
    cudaFuncSetAttribute(gemm_mma_f16<false>,
                         cudaFuncAttributeMaxDynamicSharedMemorySize, GEMM_SMEM);
    cudaFuncSetAttribute(attn_mma_f16,
                         cudaFuncAttributeMaxDynamicSharedMemorySize, ATTN_SMEM);

    const int M = B_ * S_;   // 8192

    // 0) fp32 -> fp16 prepass
    f2h_kernel<<<(B_ * S_ * D_ / 4 + 255) / 256, 256>>>(x, xh, B_ * S_ * D_ / 4);
    f2h_kernel<<<(3 * D_ * D_ / 4 + 255) / 256, 256>>>(W_attn, wah, 3 * D_ * D_ / 4);
    f2h_kernel<<<(D_ * D_ / 4 + 255) / 256, 256>>>(W_proj, wph, D_ * D_ / 4);

    // 1) QKV GEMM (fp16 mma): [8192,1024] @ [1024,3072] + bias -> fp16
    {
        dim3 grid((3 * D_) / 128, M / 128);
        gemm_mma_f16<true><<<grid, 256, GEMM_SMEM>>>(xh, wah, b_attn, qkv, 3 * D_);
    }

    // 2) Tensor-core flash attention (fp16)
    {
        dim3 grid(S_ / 128, B_ * H_);
        attn_mma_f16<<<grid, 256, ATTN_SMEM>>>(qkv, amask, attn);
    }

    // 3) Output projection (fp16 mma) -> fp32
    {
        dim3 grid(D_ / 128, M / 128);
        gemm_mma_f16<false><<<grid, 256, GEMM_SMEM>>>(attn, wph, b_proj, out, D_);
    }
}

// round 6
// speedup vs baseline: 9.3053x; 1.0748x over previous
#include <cuda_runtime.h>
#include <cuda_fp16.h>
#include <math.h>
#include <stdint.h>

// Problem constants
#define B_   8
#define S_   1024
#define D_   1024
#define H_   8
#define HD_  128
#define PREFIX_LEN 77
#define MASKED_BIAS -10000.0f

// Scratch (no cudaMalloc allowed)
__device__ __half g_xh[B_ * S_ * D_];          // x fp16           16 MB
__device__ __half g_wah[D_ * 3 * D_];          // W_attn fp16       6 MB
__device__ __half g_wph[D_ * D_];              // W_proj fp16       2 MB
__device__ __half g_qkv[B_ * S_ * 3 * D_];     // qkv fp16         48 MB
__device__ __half g_attn[B_ * S_ * D_];        // attn out fp16    16 MB

// ===========================================================================
// helpers
// ===========================================================================
__device__ __forceinline__ uint32_t s2u(const void* p) {
    return (uint32_t)__cvta_generic_to_shared((void*)p);
}
#define CP_ASYNC16(dst_u32, src_ptr) \
    asm volatile("cp.async.cg.shared.global [%0], [%1], 16;" \
                 :: "r"(dst_u32), "l"(src_ptr))
#define CP_COMMIT() asm volatile("cp.async.commit_group;" ::: "memory")
#define CP_WAIT0()  asm volatile("cp.async.wait_group 0;"  ::: "memory")
#define CP_WAIT1()  asm volatile("cp.async.wait_group 1;"  ::: "memory")
#define CP_WAIT2()  asm volatile("cp.async.wait_group 2;"  ::: "memory")

#define LDSM_X4(r0, r1, r2, r3, addr) \
    asm volatile("ldmatrix.sync.aligned.m8n8.x4.shared.b16 {%0,%1,%2,%3}, [%4];" \
        : "=r"(r0), "=r"(r1), "=r"(r2), "=r"(r3) : "r"(addr))
#define LDSM_X4_T(r0, r1, r2, r3, addr) \
    asm volatile("ldmatrix.sync.aligned.m8n8.x4.trans.shared.b16 {%0,%1,%2,%3}, [%4];" \
        : "=r"(r0), "=r"(r1), "=r"(r2), "=r"(r3) : "r"(addr))

#define MMA_F16(d, a0, a1, a2, a3, b0, b1) \
    asm volatile( \
        "mma.sync.aligned.m16n8k16.row.col.f32.f16.f16.f32 " \
        "{%0,%1,%2,%3}, {%4,%5,%6,%7}, {%8,%9}, {%0,%1,%2,%3};" \
        : "+f"((d)[0]), "+f"((d)[1]), "+f"((d)[2]), "+f"((d)[3]) \
        : "r"(a0), "r"(a1), "r"(a2), "r"(a3), "r"(b0), "r"(b1))

__device__ __forceinline__ uint32_t h2u(__half2 v) {
    return *(uint32_t*)&v;
}

// ===========================================================================
// fused fp32 -> fp16 conversion prepass (x, W_attn, W_proj in one launch)
// ===========================================================================
#define N4_X  (B_ * S_ * D_ / 4)        // 2097152
#define N4_WA (3 * D_ * D_ / 4)         // 786432
#define N4_WP (D_ * D_ / 4)             // 262144
#define N4_TOTAL (N4_X + N4_WA + N4_WP)

__global__ __launch_bounds__(256) void f2h_all(
    const float* __restrict__ x, const float* __restrict__ wa,
    const float* __restrict__ wp,
    __half* __restrict__ xh, __half* __restrict__ wah, __half* __restrict__ wph)
{
    int i = blockIdx.x * blockDim.x + threadIdx.x;
    if (i >= N4_TOTAL) return;
    const float* src;
    __half* dst;
    int j;
    if (i < N4_X)            { src = x;  dst = xh;  j = i; }
    else if (i < N4_X + N4_WA) { src = wa; dst = wah; j = i - N4_X; }
    else                     { src = wp; dst = wph; j = i - N4_X - N4_WA; }
    float4 v = ((const float4*)src)[j];
    __half2* d2 = (__half2*)dst;
    d2[2 * j]     = __floats2half2_rn(v.x, v.y);
    d2[2 * j + 1] = __floats2half2_rn(v.z, v.w);
}

// ===========================================================================
// FP16 mma GEMM (unchanged from round 5 — proven 314 TF/s)
// ===========================================================================
#define KKg 1024
#define BKg 32
#define NCHg (KKg / BKg)
#define SA_H 40
#define SB_H 136
#define A_BYTES (128 * SA_H * 2)
#define B_BYTES (BKg * SB_H * 2)
#define STAGE_BYTES (A_BYTES + B_BYTES)
#define GEMM_SMEM (4 * STAGE_BYTES)

template <bool OUT_HALF>
__global__ __launch_bounds__(256, 2) void gemm_mma_f16(
    const __half* __restrict__ A, const __half* __restrict__ Bw,
    const float* __restrict__ bias, void* __restrict__ Cv, int N)
{
    extern __shared__ char smraw[];
    const uint32_t su = s2u(smraw);

    const int t    = threadIdx.x;
    const int wid  = t >> 5;
    const int lane = t & 31;
    const int g    = lane >> 2;
    const int tq   = lane & 3;
    const int wm   = wid >> 2;
    const int wn   = wid & 3;
    const int m0   = blockIdx.y * 128;
    const int n0   = blockIdx.x * 128;

    const int l15  = lane & 15;
    const int l7   = lane & 7;
    const int hi8a = (lane & 16) ? 8 : 0;
    const int hi8b = (lane & 8)  ? 8 : 0;

    auto load_chunk = [&](int ch, int stg) {
        const int k0 = ch * BKg;
        const uint32_t base = su + (uint32_t)stg * STAGE_BYTES;
        #pragma unroll
        for (int i = 0; i < 2; i++) {
            int idx = t + i * 256;
            int r = idx >> 2, c = idx & 3;
            uint32_t dst = base + (uint32_t)(r * (SA_H * 2) + c * 16);
            const __half* src = A + (long)(m0 + r) * KKg + k0 + c * 8;
            CP_ASYNC16(dst, src);
        }
        #pragma unroll
        for (int i = 0; i < 2; i++) {
            int idx = t + i * 256;
            int r = idx >> 4, c = idx & 15;
            uint32_t dst = base + A_BYTES + (uint32_t)(r * (SB_H * 2) + c * 16);
            const __half* src = Bw + (long)(k0 + r) * N + n0 + c * 8;
            CP_ASYNC16(dst, src);
        }
    };

    #pragma unroll
    for (int c = 0; c < 3; c++) { load_chunk(c, c); CP_COMMIT(); }

    float acc[4][4][4];
    #pragma unroll
    for (int mt = 0; mt < 4; mt++)
        #pragma unroll
        for (int nt = 0; nt < 4; nt++)
            #pragma unroll
            for (int r = 0; r < 4; r++) acc[mt][nt][r] = 0.0f;

    for (int i = 0; i < NCHg; i++) {
        CP_WAIT2();
        __syncthreads();

        if (i + 3 < NCHg) load_chunk(i + 3, (i + 3) & 3);
        CP_COMMIT();

        const uint32_t sa = su + (uint32_t)(i & 3) * STAGE_BYTES;
        const uint32_t sb = sa + A_BYTES;

        #pragma unroll
        for (int ks = 0; ks < 2; ks++) {
            uint32_t af[4][4], bf[4][2];
            #pragma unroll
            for (int mt = 0; mt < 4; mt++) {
                uint32_t addr = sa + 2u * (uint32_t)(
                    (wm * 64 + mt * 16 + l15) * SA_H + ks * 16 + hi8a);
                LDSM_X4(af[mt][0], af[mt][1], af[mt][2], af[mt][3], addr);
            }
            #pragma unroll
            for (int np = 0; np < 2; np++) {
                uint32_t addr = sb + 2u * (uint32_t)(
                    (ks * 16 + l7 + hi8b) * SB_H + wn * 32 + np * 16 + hi8a);
                LDSM_X4_T(bf[2 * np][0], bf[2 * np][1],
                          bf[2 * np + 1][0], bf[2 * np + 1][1], addr);
            }
            #pragma unroll
            for (int mt = 0; mt < 4; mt++)
                #pragma unroll
                for (int nt = 0; nt < 4; nt++)
                    MMA_F16(acc[mt][nt], af[mt][0], af[mt][1], af[mt][2],
                            af[mt][3], bf[nt][0], bf[nt][1]);
        }
    }

    #pragma unroll
    for (int nt = 0; nt < 4; nt++) {
        const int col = n0 + wn * 32 + nt * 8 + tq * 2;
        const float bx = bias[col];
        const float by = bias[col + 1];
        #pragma unroll
        for (int mt = 0; mt < 4; mt++) {
            const int row = m0 + wm * 64 + mt * 16 + g;
            if (OUT_HALF) {
                __half* C = (__half*)Cv;
                *(__half2*)&C[(long)row * N + col] =
                    __floats2half2_rn(acc[mt][nt][0] + bx, acc[mt][nt][1] + by);
                *(__half2*)&C[(long)(row + 8) * N + col] =
                    __floats2half2_rn(acc[mt][nt][2] + bx, acc[mt][nt][3] + by);
            } else {
                float* C = (float*)Cv;
                *(float2*)&C[(long)row * N + col] =
                    make_float2(acc[mt][nt][0] + bx, acc[mt][nt][1] + by);
                *(float2*)&C[(long)(row + 8) * N + col] =
                    make_float2(acc[mt][nt][2] + bx, acc[mt][nt][3] + by);
            }
        }
    }
}

// ===========================================================================
// FP16 tensor-core flash attention, cp.async pipelined, P-in-fragments.
// Grid: (S/128, B*H). 8 warps, warp = 16 query rows. Key tiles 64, causal
// tile skipping, fp32 softmax in registers.
// SMEM: Q[128][136] + 2 stages of (K[64][136] + V[64][136]).
// ===========================================================================
#define AST 136                            // row stride (halves)
#define Q_OFF 0
#define KV_STAGE (64 * AST * 2)            // K+V per stage (halves) = 17408
#define KV_OFF (128 * AST)                 // 17408
#define ATTN_SMEM ((KV_OFF + 2 * KV_STAGE) * 2)   // 104448 bytes

__global__ __launch_bounds__(256, 1) void attn_mma_f16(
    const __half* __restrict__ qkv,     // [B,S,3D] fp16
    const float* __restrict__ amask,    // [B,1,1,S] fp32
    __half* __restrict__ aout)          // [B,S,D] fp16
{
    extern __shared__ __half smh[];
    const uint32_t su = s2u(smh);
    const uint32_t Qu = su;

    const int t    = threadIdx.x;
    const int wid  = t >> 5;
    const int lane = t & 31;
    const int g    = lane >> 2;
    const int tq   = lane & 3;
    // largest-work blocks first (they have the most causal tiles)
    const int qt   = gridDim.x - 1 - blockIdx.x;
    const int q0   = qt * 128;
    const int bh   = blockIdx.y;
    const int b    = bh >> 3;
    const int h    = bh & 7;
    const int rb   = wid * 16;

    const int l15  = lane & 15;
    const int l7   = lane & 7;
    const int hi8a = (lane & 16) ? 8 : 0;
    const int hi8b = (lane & 8)  ? 8 : 0;

    const float qscale = rsqrtf((float)HD_);
    const int nkt = q0 / 64 + 2;        // causal tile limit

    // ---- issue Q tile load (cp.async group 0) ----
    #pragma unroll
    for (int i = 0; i < 8; i++) {
        int idx = t + i * 256;          // 0..2047
        int row = idx >> 4;
        int c   = idx & 15;
        uint32_t dst = su + 2u * (uint32_t)(Q_OFF + row * AST + c * 8);
        CP_ASYNC16(dst, &qkv[(long)(b * S_ + q0 + row) * (3 * D_) + h * HD_ + c * 8]);
    }
    CP_COMMIT();

    // ---- KV tile loader ----
    auto load_kv = [&](int kt, int stg) {
        const uint32_t kbase = su + 2u * (uint32_t)(KV_OFF + stg * KV_STAGE);
        #pragma unroll
        for (int i = 0; i < 8; i++) {
            int idx = t + i * 256;       // 0..2047 ; first 1024 = K, rest = V
            int row = (idx & 1023) >> 4;
            int c   = idx & 15;
            long src = (long)(b * S_ + kt * 64 + row) * (3 * D_) + h * HD_ + c * 8;
            if (idx < 1024) {
                CP_ASYNC16(kbase + 2u * (uint32_t)(row * AST + c * 8),
                           &qkv[src + D_]);
            } else {
                CP_ASYNC16(kbase + 2u * (uint32_t)((64 + row) * AST + c * 8),
                           &qkv[src + 2 * D_]);
            }
        }
        CP_COMMIT();
    };

    load_kv(0, 0);

    // ---- wait Q (group pending: KV0), hoist Q fragments ----
    CP_WAIT1();
    __syncthreads();
    uint32_t qf[8][4];
    #pragma unroll
    for (int ks = 0; ks < 8; ks++) {
        LDSM_X4(qf[ks][0], qf[ks][1], qf[ks][2], qf[ks][3],
                Qu + 2u * (uint32_t)((rb + l15) * AST + ks * 16 + hi8a));
    }

    float o[16][4];
    #pragma unroll
    for (int nt = 0; nt < 16; nt++)
        #pragma unroll
        for (int r = 0; r < 4; r++) o[nt][r] = 0.0f;
    float m0 = -1e30f, m1 = -1e30f, l0 = 0.0f, l1 = 0.0f;

    const int row0 = q0 + rb + g;
    const int row1 = row0 + 8;

    for (int kt = 0; kt < nkt; kt++) {
        // prefetch next tile into the other stage, then wait for current
        if (kt + 1 < nkt) { load_kv(kt + 1, (kt + 1) & 1); CP_WAIT1(); }
        else              { CP_WAIT0(); }
        __syncthreads();

        const uint32_t Ku = su + 2u * (uint32_t)(KV_OFF + (kt & 1) * KV_STAGE);
        const uint32_t Vu = Ku + 2u * (uint32_t)(64 * AST);

        // ---- S = Q @ K^T : warp tile 16x64 ----
        float sacc[8][4];
        #pragma unroll
        for (int nt = 0; nt < 8; nt++)
            #pragma unroll
            for (int r = 0; r < 4; r++) sacc[nt][r] = 0.0f;

        #pragma unroll
        for (int ks = 0; ks < 8; ks++) {
            #pragma unroll
            for (int np = 0; np < 4; np++) {
                uint32_t b0, b1, b2, b3;
                LDSM_X4(b0, b1, b2, b3,
                        Ku + 2u * (uint32_t)((np * 16 + l7 + hi8a) * AST + ks * 16 + hi8b));
                MMA_F16(sacc[2 * np],     qf[ks][0], qf[ks][1], qf[ks][2], qf[ks][3], b0, b1);
                MMA_F16(sacc[2 * np + 1], qf[ks][0], qf[ks][1], qf[ks][2], qf[ks][3], b2, b3);
            }
        }

        // ---- scale + mask + online softmax (fp32, registers) ----
        float mloc0 = -1e30f, mloc1 = -1e30f;
        #pragma unroll
        for (int nt = 0; nt < 8; nt++) {
            const int c0 = kt * 64 + nt * 8 + 2 * tq;
            const int c1 = c0 + 1;
            const float am0 = amask[b * S_ + c0];
            const float am1 = amask[b * S_ + c1];
            bool ok00 = (row0 < PREFIX_LEN) ? (c0 < PREFIX_LEN) : (c0 <= row0);
            bool ok01 = (row0 < PREFIX_LEN) ? (c1 < PREFIX_LEN) : (c1 <= row0);
            bool ok10 = (row1 < PREFIX_LEN) ? (c0 < PREFIX_LEN) : (c0 <= row1);
            bool ok11 = (row1 < PREFIX_LEN) ? (c1 < PREFIX_LEN) : (c1 <= row1);
            sacc[nt][0] = (ok00 ? sacc[nt][0] * qscale : MASKED_BIAS) + am0;
            sacc[nt][1] = (ok01 ? sacc[nt][1] * qscale : MASKED_BIAS) + am1;
            sacc[nt][2] = (ok10 ? sacc[nt][2] * qscale : MASKED_BIAS) + am0;
            sacc[nt][3] = (ok11 ? sacc[nt][3] * qscale : MASKED_BIAS) + am1;
            mloc0 = fmaxf(mloc0, fmaxf(sacc[nt][0], sacc[nt][1]));
            mloc1 = fmaxf(mloc1, fmaxf(sacc[nt][2], sacc[nt][3]));
        }
        mloc0 = fmaxf(mloc0, __shfl_xor_sync(0xFFFFFFFF, mloc0, 1));
        mloc0 = fmaxf(mloc0, __shfl_xor_sync(0xFFFFFFFF, mloc0, 2));
        mloc1 = fmaxf(mloc1, __shfl_xor_sync(0xFFFFFFFF, mloc1, 1));
        mloc1 = fmaxf(mloc1, __shfl_xor_sync(0xFFFFFFFF, mloc1, 2));

        const float mn0 = fmaxf(m0, mloc0);
        const float mn1 = fmaxf(m1, mloc1);
        const float sc0 = __expf(m0 - mn0);
        const float sc1 = __expf(m1 - mn1);
        m0 = mn0; m1 = mn1;

        float ls0 = 0.0f, ls1 = 0.0f;
        #pragma unroll
        for (int nt = 0; nt < 8; nt++) {
            sacc[nt][0] = __expf(sacc[nt][0] - mn0);
            sacc[nt][1] = __expf(sacc[nt][1] - mn0);
            sacc[nt][2] = __expf(sacc[nt][2] - mn1);
            sacc[nt][3] = __expf(sacc[nt][3] - mn1);
            ls0 += sacc[nt][0] + sacc[nt][1];
            ls1 += sacc[nt][2] + sacc[nt][3];
        }
        ls0 += __shfl_xor_sync(0xFFFFFFFF, ls0, 1);
        ls0 += __shfl_xor_sync(0xFFFFFFFF, ls0, 2);
        ls1 += __shfl_xor_sync(0xFFFFFFFF, ls1, 1);
        ls1 += __shfl_xor_sync(0xFFFFFFFF, ls1, 2);
        l0 = l0 * sc0 + ls0;
        l1 = l1 * sc1 + ls1;

        #pragma unroll
        for (int nt = 0; nt < 16; nt++) {
            o[nt][0] *= sc0; o[nt][1] *= sc0;
            o[nt][2] *= sc1; o[nt][3] *= sc1;
        }

        // ---- O += P @ V : P stays in registers (C-frag pair == A-frag) ----
        #pragma unroll
        for (int kk = 0; kk < 4; kk++) {
            uint32_t pa0 = h2u(__floats2half2_rn(sacc[2 * kk][0],     sacc[2 * kk][1]));
            uint32_t pa1 = h2u(__floats2half2_rn(sacc[2 * kk][2],     sacc[2 * kk][3]));
            uint32_t pa2 = h2u(__floats2half2_rn(sacc[2 * kk + 1][0], sacc[2 * kk + 1][1]));
            uint32_t pa3 = h2u(__floats2half2_rn(sacc[2 * kk + 1][2], sacc[2 * kk + 1][3]));
            #pragma unroll
            for (int np = 0; np < 8; np++) {
                uint32_t b0, b1, b2, b3;
                LDSM_X4_T(b0, b1, b2, b3,
                          Vu + 2u * (uint32_t)((kk * 16 + l7 + hi8b) * AST + np * 16 + hi8a));
                MMA_F16(o[2 * np],     pa0, pa1, pa2, pa3, b0, b1);
                MMA_F16(o[2 * np + 1], pa0, pa1, pa2, pa3, b2, b3);
            }
        }

        __syncthreads();   // all warps done with this stage before overwrite
    }

    // ---- epilogue ----
    const float inv0 = 1.0f / l0;
    const float inv1 = 1.0f / l1;
    #pragma unroll
    for (int nt = 0; nt < 16; nt++) {
        const int col = h * HD_ + nt * 8 + 2 * tq;
        *(__half2*)&aout[(long)(b * S_ + row0) * D_ + col] =
            __floats2half2_rn(o[nt][0] * inv0, o[nt][1] * inv0);
        *(__half2*)&aout[(long)(b * S_ + row1) * D_ + col] =
            __floats2half2_rn(o[nt][2] * inv1, o[nt][3] * inv1);
    }
}

// ===========================================================================
extern "C" void kernel_launch(void* const* d_in, const int* in_sizes, int n_in,
                              void* d_out, int out_size)
{
    const float* x      = (const float*)d_in[0];
    const float* amask  = (const float*)d_in[1];
    const float* W_attn = (const float*)d_in[2];
    const float* b_attn = (const float*)d_in[3];
    const float* W_proj = (const float*)d_in[4];
    const float* b_proj = (const float*)d_in[5];
    float* out = (float*)d_out;

    __half *xh, *wah, *wph, *qkv, *attn;
    cudaGetSymbolAddress((void**)&xh,   g_xh);
    cudaGetSymbolAddress((void**)&wah,  g_wah);
    cudaGetSymbolAddress((void**)&wph,  g_wph);
    cudaGetSymbolAddress((void**)&qkv,  g_qkv);
    cudaGetSymbolAddress((void**)&attn, g_attn);

    cudaFuncSetAttribute(gemm_mma_f16<true>,
                         cudaFuncAttributeMaxDynamicSharedMemorySize, GEMM_SMEM);
    cudaFuncSetAttribute(gemm_mma_f16<false>,
                         cudaFuncAttributeMaxDynamicSharedMemorySize, GEMM_SMEM);
    cudaFuncSetAttribute(attn_mma_f16,
                         cudaFuncAttributeMaxDynamicSharedMemorySize, ATTN_SMEM);

    const int M = B_ * S_;   // 8192

    // 0) fused fp32 -> fp16 prepass
    f2h_all<<<(N4_TOTAL + 255) / 256, 256>>>(x, W_attn, W_proj, xh, wah, wph);

    // 1) QKV GEMM (fp16 mma) -> fp16
    {
        dim3 grid((3 * D_) / 128, M / 128);
        gemm_mma_f16<true><<<grid, 256, GEMM_SMEM>>>(xh, wah, b_attn, qkv, 3 * D_);
    }

    // 2) Tensor-core flash attention (fp16, cp.async pipelined)
    {
        dim3 grid(S_ / 128, B_ * H_);
        attn_mma_f16<<<grid, 256, ATTN_SMEM>>>(qkv, amask, attn);
    }

    // 3) Output projection (fp16 mma) -> fp32
    {
        dim3 grid(D_ / 128, M / 128);
        gemm_mma_f16<false><<<grid, 256, GEMM_SMEM>>>(attn, wph, b_proj, out, D_);
    }
}